// round 14
// baseline (speedup 1.0000x reference)
#include <cuda_runtime.h>
#include <math.h>
#include <stdint.h>

#define NB 8
#define NT 2048
#define NC 1024
#define NH 64
#define QSCALE 0.125f    // 64^-0.5
#define NTILES (NT / 64) // 32

// Scratch for projections.
__device__ float g_q[NB * NT * NH];
__device__ float g_k[NB * NT * NH];
__device__ float g_v[NB * NT * NH];

// ============================================================================
// Packed f32x2 + cp.async helpers (family-level PTX).
// ============================================================================
__device__ __forceinline__ void fma2(uint64_t& d, uint64_t a, uint64_t b) {
    asm("fma.rn.f32x2 %0, %1, %2, %0;" : "+l"(d) : "l"(a), "l"(b));
}
__device__ __forceinline__ void mul2(uint64_t& d, uint64_t a) {
    asm("mul.rn.f32x2 %0, %0, %1;" : "+l"(d) : "l"(a));
}
__device__ __forceinline__ uint64_t pack2(float x, float y) {
    uint64_t r;
    asm("mov.b64 %0, {%1, %2};" : "=l"(r)
        : "r"(__float_as_uint(x)), "r"(__float_as_uint(y)));
    return r;
}
__device__ __forceinline__ uint64_t dup2(float x) { return pack2(x, x); }
__device__ __forceinline__ float2 unpack2(uint64_t p) {
    uint32_t lo, hi;
    asm("mov.b64 {%0, %1}, %2;" : "=r"(lo), "=r"(hi) : "l"(p));
    return make_float2(__uint_as_float(lo), __uint_as_float(hi));
}
__device__ __forceinline__ void f4_pairs(const float4& v, uint64_t& p0, uint64_t& p1) {
    p0 = pack2(v.x, v.y);
    p1 = pack2(v.z, v.w);
}
__device__ __forceinline__ uint32_t smem_u32(const void* p) {
    uint32_t a;
    asm("{ .reg .u64 t; cvta.to.shared.u64 t, %1; cvt.u32.u64 %0, t; }"
        : "=r"(a) : "l"(p));
    return a;
}
__device__ __forceinline__ void cp_async16(uint32_t dst, const void* src) {
    asm volatile("cp.async.cg.shared.global [%0], [%1], 16;"
                 :: "r"(dst), "l"(src) : "memory");
}
#define CP_COMMIT() asm volatile("cp.async.commit_group;" ::: "memory")
#define CP_WAIT0()  asm volatile("cp.async.wait_group 0;" ::: "memory")

// ---------------------------------------------------------------------------
// Fused projection GEMM (R12 proven): {q,k,v} = x @ {wq,wk,wv}, FFMA2.
// ---------------------------------------------------------------------------
#define PBK 16
#define PAP 132
#define PBP 196

__global__ __launch_bounds__(256) void proj_kernel(
    const float* __restrict__ x,
    const float* __restrict__ wq,
    const float* __restrict__ wk,
    const float* __restrict__ wv)
{
    __shared__ float sA[2][PBK][PAP];
    __shared__ float sB[2][PBK][PBP];

    const int m0  = blockIdx.x * 128;
    const int tid = threadIdx.x;
    const int tr  = tid >> 4;
    const int tc  = tid & 15;

    const float* wsel[3] = {wq, wk, wv};
    float*       dsel[3] = {g_q, g_k, g_v};

    uint64_t acc2[8][6];
    #pragma unroll
    for (int i = 0; i < 8; i++)
        #pragma unroll
        for (int j = 0; j < 6; j++) acc2[i][j] = 0ull;

    float4 ar[2], br[3];
    #pragma unroll
    for (int u = 0; u < 2; u++) {
        int f = tid * 2 + u;
        int r = f >> 2, c4 = f & 3;
        ar[u] = *(const float4*)&x[(size_t)(m0 + r) * NC + c4 * 4];
    }
    #pragma unroll
    for (int u = 0; u < 3; u++) {
        int f  = tid * 3 + u;
        int kk = f / 48, c4 = f % 48;
        int col = c4 * 4;
        br[u] = *(const float4*)&wsel[col >> 6][(size_t)kk * NH + (col & 63)];
    }
    #pragma unroll
    for (int u = 0; u < 2; u++) {
        int f = tid * 2 + u;
        int r = f >> 2, c4 = f & 3;
        sA[0][c4 * 4 + 0][r] = ar[u].x;
        sA[0][c4 * 4 + 1][r] = ar[u].y;
        sA[0][c4 * 4 + 2][r] = ar[u].z;
        sA[0][c4 * 4 + 3][r] = ar[u].w;
    }
    #pragma unroll
    for (int u = 0; u < 3; u++) {
        int f  = tid * 3 + u;
        int kk = f / 48, c4 = f % 48;
        *(float4*)&sB[0][kk][c4 * 4] = br[u];
    }
    __syncthreads();

    const int NSTEP = NC / PBK;
    for (int ks = 0; ks < NSTEP; ks++) {
        int cur = ks & 1;
        if (ks + 1 < NSTEP) {
            int k0 = (ks + 1) * PBK;
            #pragma unroll
            for (int u = 0; u < 2; u++) {
                int f = tid * 2 + u;
                int r = f >> 2, c4 = f & 3;
                ar[u] = *(const float4*)&x[(size_t)(m0 + r) * NC + k0 + c4 * 4];
            }
            #pragma unroll
            for (int u = 0; u < 3; u++) {
                int f  = tid * 3 + u;
                int kk = f / 48, c4 = f % 48;
                int col = c4 * 4;
                br[u] = *(const float4*)&wsel[col >> 6][(size_t)(k0 + kk) * NH + (col & 63)];
            }
        }
        #pragma unroll
        for (int kk = 0; kk < PBK; kk++) {
            float a[8];
            float4 b0, b1, b2;
            *(float4*)&a[0] = *(float4*)&sA[cur][kk][tr * 8];
            *(float4*)&a[4] = *(float4*)&sA[cur][kk][tr * 8 + 4];
            b0 = *(float4*)&sB[cur][kk][tc * 12];
            b1 = *(float4*)&sB[cur][kk][tc * 12 + 4];
            b2 = *(float4*)&sB[cur][kk][tc * 12 + 8];
            uint64_t bP[6];
            f4_pairs(b0, bP[0], bP[1]);
            f4_pairs(b1, bP[2], bP[3]);
            f4_pairs(b2, bP[4], bP[5]);
            #pragma unroll
            for (int i = 0; i < 8; i++) {
                uint64_t aD = dup2(a[i]);
                #pragma unroll
                for (int j = 0; j < 6; j++)
                    fma2(acc2[i][j], aD, bP[j]);
            }
        }
        if (ks + 1 < NSTEP) {
            int nxt = cur ^ 1;
            #pragma unroll
            for (int u = 0; u < 2; u++) {
                int f = tid * 2 + u;
                int r = f >> 2, c4 = f & 3;
                sA[nxt][c4 * 4 + 0][r] = ar[u].x;
                sA[nxt][c4 * 4 + 1][r] = ar[u].y;
                sA[nxt][c4 * 4 + 2][r] = ar[u].z;
                sA[nxt][c4 * 4 + 3][r] = ar[u].w;
            }
            #pragma unroll
            for (int u = 0; u < 3; u++) {
                int f  = tid * 3 + u;
                int kk = f / 48, c4 = f % 48;
                *(float4*)&sB[nxt][kk][c4 * 4] = br[u];
            }
        }
        __syncthreads();
    }

    #pragma unroll
    for (int i = 0; i < 8; i++) {
        int r = m0 + tr * 8 + i;
        #pragma unroll
        for (int g = 0; g < 3; g++) {
            int col = tc * 12 + g * 4;
            float* dst = dsel[col >> 6];
            float2 t0 = unpack2(acc2[i][2 * g]);
            float2 t1 = unpack2(acc2[i][2 * g + 1]);
            *(float4*)&dst[(size_t)r * NH + (col & 63)] =
                make_float4(t0.x, t0.y, t1.x, t1.y);
        }
    }
}

// ---------------------------------------------------------------------------
// Causal flash attention v7: 128 threads/CTA, 8x4 thread tile (FFMA2),
// sequential tile pair (31-p, p), K reg-prefetch, V cp.async double buffer.
// grid = (16, 8).
// ---------------------------------------------------------------------------
#define PITCH 68
struct AttnSmem {
    float qT[64][PITCH];     // qT[h][row], pre-scaled
    float kT[2][64][PITCH];  // kT[h][col]
    float v [2][64][PITCH];  // v[token][h]
    float sT[64][PITCH];     // P transposed: sT[col][row]
};

extern __shared__ char attn_smem_raw[];

__device__ __forceinline__ void attn_tile(
    AttnSmem* sm, const float* Qb, const float* Kb, const float* Vb,
    float* out, int b, int it, int tid, int ty, int tx)
{
    // ---- load Q tile transposed, pre-scaled (8 float4 / thread) ----
    #pragma unroll
    for (int u = 0; u < 8; u++) {
        int f  = u * 128 + tid;
        int r  = f >> 4;
        int c4 = f & 15;
        float4 t = *(const float4*)&Qb[(size_t)(it * 64 + r) * NH + c4 * 4];
        sm->qT[c4 * 4 + 0][r] = t.x * QSCALE;
        sm->qT[c4 * 4 + 1][r] = t.y * QSCALE;
        sm->qT[c4 * 4 + 2][r] = t.z * QSCALE;
        sm->qT[c4 * 4 + 3][r] = t.w * QSCALE;
    }
    // ---- KV tile 0 into buffer 0 (K transposed STS, V cp.async) ----
    #pragma unroll
    for (int u = 0; u < 8; u++) {
        int f  = u * 128 + tid;
        int r  = f >> 4;
        int c4 = f & 15;
        size_t gb = (size_t)r * NH + c4 * 4;
        cp_async16(smem_u32(&sm->v[0][r][c4 * 4]), &Vb[gb]);
        float4 tk = *(const float4*)&Kb[gb];
        sm->kT[0][c4 * 4 + 0][r] = tk.x;
        sm->kT[0][c4 * 4 + 1][r] = tk.y;
        sm->kT[0][c4 * 4 + 2][r] = tk.z;
        sm->kT[0][c4 * 4 + 3][r] = tk.w;
    }
    CP_COMMIT();
    CP_WAIT0();
    __syncthreads();

    uint64_t o2[4][4];       // [row-pair][col], lanes (row 2p, 2p+1)
    float m[8], l[8];
    #pragma unroll
    for (int p = 0; p < 4; p++)
        #pragma unroll
        for (int j = 0; j < 4; j++) o2[p][j] = 0ull;
    #pragma unroll
    for (int i = 0; i < 8; i++) { m[i] = -INFINITY; l[i] = 0.f; }

    for (int jt = 0; jt <= it; jt++) {
        int cur = jt & 1;
        int nxt = cur ^ 1;

        // prefetch next KV: V via cp.async, K into registers
        float4 kr[8];
        if (jt < it) {
            #pragma unroll
            for (int u = 0; u < 8; u++) {
                int f  = u * 128 + tid;
                int r  = f >> 4;
                int c4 = f & 15;
                size_t gb = (size_t)((jt + 1) * 64 + r) * NH + c4 * 4;
                cp_async16(smem_u32(&sm->v[nxt][r][c4 * 4]), &Vb[gb]);
                kr[u] = *(const float4*)&Kb[gb];
            }
            CP_COMMIT();
        }

        // ---- S = Q @ K^T : 8x4 via row-pair FFMA2 ----
        uint64_t acc2[4][4];
        #pragma unroll
        for (int p = 0; p < 4; p++)
            #pragma unroll
            for (int j = 0; j < 4; j++) acc2[p][j] = 0ull;
        #pragma unroll
        for (int kk = 0; kk < 64; kk++) {
            float4 qa = *(float4*)&sm->qT[kk][ty * 8];
            float4 qb = *(float4*)&sm->qT[kk][ty * 8 + 4];
            float4 k4 = *(float4*)&sm->kT[cur][kk][tx * 4];
            uint64_t aP[4];
            f4_pairs(qa, aP[0], aP[1]);
            f4_pairs(qb, aP[2], aP[3]);
            uint64_t kD[4] = {dup2(k4.x), dup2(k4.y), dup2(k4.z), dup2(k4.w)};
            #pragma unroll
            for (int p = 0; p < 4; p++)
                #pragma unroll
                for (int j = 0; j < 4; j++)
                    fma2(acc2[p][j], aP[p], kD[j]);
        }

        // ---- unpack, mask ----
        float acc[8][4];
        #pragma unroll
        for (int p = 0; p < 4; p++)
            #pragma unroll
            for (int j = 0; j < 4; j++) {
                float2 t = unpack2(acc2[p][j]);
                acc[2 * p    ][j] = t.x;
                acc[2 * p + 1][j] = t.y;
            }
        if (jt == it) {
            #pragma unroll
            for (int i = 0; i < 8; i++) {
                int qi = ty * 8 + i;
                #pragma unroll
                for (int j = 0; j < 4; j++)
                    if (tx * 4 + j > qi) acc[i][j] = -INFINITY;
            }
        }

        // ---- online softmax (16-lane reductions; lanes (ty&1)*16+tx) ----
        float alpha[8], pr[8][4];
        #pragma unroll
        for (int i = 0; i < 8; i++) {
            float v = fmaxf(fmaxf(acc[i][0], acc[i][1]),
                            fmaxf(acc[i][2], acc[i][3]));
            #pragma unroll
            for (int d = 1; d < 16; d <<= 1)
                v = fmaxf(v, __shfl_xor_sync(0xffffffffu, v, d));
            float mn = fmaxf(m[i], v);
            alpha[i] = __expf(m[i] - mn);
            m[i] = mn;
            float rs = 0.f;
            #pragma unroll
            for (int j = 0; j < 4; j++) {
                pr[i][j] = __expf(acc[i][j] - mn);
                rs += pr[i][j];
            }
            #pragma unroll
            for (int d = 1; d < 16; d <<= 1)
                rs += __shfl_xor_sync(0xffffffffu, rs, d);
            l[i] = l[i] * alpha[i] + rs;
        }
        // O *= alpha (packed row pairs)
        #pragma unroll
        for (int p = 0; p < 4; p++) {
            uint64_t aPk = pack2(alpha[2 * p], alpha[2 * p + 1]);
            #pragma unroll
            for (int j = 0; j < 4; j++) mul2(o2[p][j], aPk);
        }

        // ---- stage P transposed (crosses warps -> block barrier) ----
        #pragma unroll
        for (int j = 0; j < 4; j++) {
            *(float4*)&sm->sT[tx * 4 + j][ty * 8] =
                make_float4(pr[0][j], pr[1][j], pr[2][j], pr[3][j]);
            *(float4*)&sm->sT[tx * 4 + j][ty * 8 + 4] =
                make_float4(pr[4][j], pr[5][j], pr[6][j], pr[7][j]);
        }
        __syncthreads();

        // ---- O += P @ V : row-pair FFMA2 ----
        #pragma unroll
        for (int kk = 0; kk < 64; kk++) {
            float4 pa = *(float4*)&sm->sT[kk][ty * 8];
            float4 pb = *(float4*)&sm->sT[kk][ty * 8 + 4];
            float4 v4 = *(float4*)&sm->v[cur][kk][tx * 4];
            uint64_t pP[4];
            f4_pairs(pa, pP[0], pP[1]);
            f4_pairs(pb, pP[2], pP[3]);
            uint64_t vD[4] = {dup2(v4.x), dup2(v4.y), dup2(v4.z), dup2(v4.w)};
            #pragma unroll
            for (int p = 0; p < 4; p++)
                #pragma unroll
                for (int j = 0; j < 4; j++)
                    fma2(o2[p][j], pP[p], vD[j]);
        }

        // ---- commit prefetched K to smem; wait for V cp.async ----
        if (jt < it) {
            #pragma unroll
            for (int u = 0; u < 8; u++) {
                int f  = u * 128 + tid;
                int r  = f >> 4;
                int c4 = f & 15;
                sm->kT[nxt][c4 * 4 + 0][r] = kr[u].x;
                sm->kT[nxt][c4 * 4 + 1][r] = kr[u].y;
                sm->kT[nxt][c4 * 4 + 2][r] = kr[u].z;
                sm->kT[nxt][c4 * 4 + 3][r] = kr[u].w;
            }
            CP_WAIT0();
        }
        __syncthreads();
    }

    // ---- normalize and write (unpack row pairs) ----
    #pragma unroll
    for (int p = 0; p < 4; p++) {
        float2 c0 = unpack2(o2[p][0]);
        float2 c1 = unpack2(o2[p][1]);
        float2 c2 = unpack2(o2[p][2]);
        float2 c3 = unpack2(o2[p][3]);
        float inv0 = 1.f / l[2 * p];
        float inv1 = 1.f / l[2 * p + 1];
        size_t r0 = (size_t)b * NT + it * 64 + ty * 8 + 2 * p;
        *(float4*)&out[r0 * NH + tx * 4] =
            make_float4(c0.x * inv0, c1.x * inv0, c2.x * inv0, c3.x * inv0);
        *(float4*)&out[(r0 + 1) * NH + tx * 4] =
            make_float4(c0.y * inv1, c1.y * inv1, c2.y * inv1, c3.y * inv1);
    }
}

__global__ __launch_bounds__(128) void attn_kernel(float* __restrict__ out)
{
    AttnSmem* sm = reinterpret_cast<AttnSmem*>(attn_smem_raw);

    const int b   = blockIdx.y;
    const int p   = blockIdx.x;
    const int tid = threadIdx.x;
    const int ty  = tid >> 4;    // 0..7 -> rows ty*8..ty*8+7
    const int tx  = tid & 15;    // 0..15 -> cols tx*4..tx*4+3

    const float* Qb = g_q + (size_t)b * NT * NH;
    const float* Kb = g_k + (size_t)b * NT * NH;
    const float* Vb = g_v + (size_t)b * NT * NH;

    attn_tile(sm, Qb, Kb, Vb, out, b, NTILES - 1 - p, tid, ty, tx);
    __syncthreads();
    attn_tile(sm, Qb, Kb, Vb, out, b, p, tid, ty, tx);
}

// ---------------------------------------------------------------------------

extern "C" void kernel_launch(void* const* d_in, const int* in_sizes, int n_in,
                              void* d_out, int out_size)
{
    const float* x  = (const float*)d_in[0];
    const float* wq = (const float*)d_in[1];
    const float* wk = (const float*)d_in[2];
    const float* wv = (const float*)d_in[3];
    float* out = (float*)d_out;

    const int attn_smem = (int)sizeof(AttnSmem);
    cudaFuncSetAttribute(attn_kernel,
                         cudaFuncAttributeMaxDynamicSharedMemorySize,
                         attn_smem);

    proj_kernel<<<dim3((NB * NT) / 128), 256>>>(x, wq, wk, wv);
    attn_kernel<<<dim3(NTILES / 2, NB), 128, attn_smem>>>(out);
}